// round 10
// baseline (speedup 1.0000x reference)
#include <cuda_runtime.h>
#include <cstdint>

// PPEG: out[b,0,c] = x[b,0,c] (cls); out[b,1+p,c] = folded 7x7 depthwise conv
// (w7 + pad(w5) + pad(w3) + identity, bias b7+b5+b3) over the 64x64 map.
// R10 = R9 (best, 88.8us) with RY=4: thread = 8x4 px, tile 16x8, 128 threads.
// Window rows per output row: 2.5 (was 4) -> ~37% less L1 window traffic.

#define CH   512
#define HW   64
#define NTOK 4097

typedef unsigned long long ULL;

__device__ float g_weff[49 * CH];   // [tap][channel]
__device__ float g_bsum[CH];

// packed f32x2 FMA (sm_103a FFMA2 — only reachable via PTX)
__device__ __forceinline__ ULL ffma2(ULL a, ULL b, ULL c) {
    ULL d;
    asm("fma.rn.f32x2 %0, %1, %2, %3;" : "=l"(d) : "l"(a), "l"(b), "l"(c));
    return d;
}

// ---------------------------------------------------------------------------
// Kernel 1: weight fold + bias + cls copy, one launch.
__global__ void ppeg_prep(const float* __restrict__ w7, const float* __restrict__ b7,
                          const float* __restrict__ w5, const float* __restrict__ b5,
                          const float* __restrict__ w3, const float* __restrict__ b3,
                          const float* __restrict__ x, float* __restrict__ out) {
    const int bid = blockIdx.x;
    const int tid = threadIdx.x;
    if (bid < 98) {
        const int i = bid * 256 + tid;        // 0 .. 25087 = 512*49
        const int c = i / 49;
        const int t = i % 49;
        const int ky = t / 7, kx = t % 7;
        float v = w7[c * 49 + t];
        if (ky >= 1 && ky <= 5 && kx >= 1 && kx <= 5)
            v += w5[c * 25 + (ky - 1) * 5 + (kx - 1)];
        if (ky >= 2 && ky <= 4 && kx >= 2 && kx <= 4)
            v += w3[c * 9 + (ky - 2) * 3 + (kx - 2)];
        if (t == 24) v += 1.0f;               // identity (residual) term
        g_weff[t * CH + c] = v;
    } else if (bid < 100) {
        const int c = (bid - 98) * 256 + tid;
        g_bsum[c] = b7[c] + b5[c] + b3[c];
    } else {
        const int j = (bid - 100) * 256 + tid;   // cls: 16*512 floats
        const int b = j >> 9;
        const int cc = j & 511;
        const size_t off = (size_t)b * NTOK * CH + cc;
        out[off] = x[off];
    }
}

// ---------------------------------------------------------------------------
// Kernel 2: folded 7x7 depthwise conv.
//   lane   = channel pair (64 ch per block) -> 256B coalesced accesses
//   thread = 8x4 output pixels; warps 2x2 -> block tile 16x8 pixels
//   grid   = (4, 8, 128); weights+bias staged once to smem, LDS in FMA stream
__global__ void __launch_bounds__(128)
ppeg_conv(const float* __restrict__ x, float* __restrict__ out) {
    const int lane = threadIdx.x & 31;
    const int warp = threadIdx.x >> 5;         // 0..3
    const int wx = warp & 1;
    const int wy = warp >> 1;                  // 0..1
    const int x0 = blockIdx.x * 16 + wx * 8;   // RX=8 output cols per thread
    const int y0 = blockIdx.y * 8 + wy * 4;    // RY=4 output rows per thread
    const int b  = blockIdx.z >> 3;
    const int cg = blockIdx.z & 7;
    const int cb = cg * 64;
    const int c  = cb + lane * 2;

    // Stage this channel group's folded weights + bias into SMEM (coalesced).
    __shared__ __align__(16) float sw[49 * 64];
    __shared__ __align__(16) float sb[64];
    #pragma unroll
    for (int i = threadIdx.x; i < 49 * 64; i += 128) {
        const int t  = i >> 6;
        const int cc = i & 63;
        sw[i] = g_weff[t * CH + cb + cc];
    }
    if (threadIdx.x < 64) sb[threadIdx.x] = g_bsum[cb + threadIdx.x];
    __syncthreads();

    const ULL bias = *reinterpret_cast<const ULL*>(&sb[lane * 2]);

    ULL acc[4][8];
    #pragma unroll
    for (int ry = 0; ry < 4; ++ry)
        #pragma unroll
        for (int rx = 0; rx < 8; ++rx)
            acc[ry][rx] = bias;

    const float* xb = x + ((size_t)b * NTOK + 1) * CH + c;
    const float* wbase = xb + ((size_t)(y0 - 3) * HW + (x0 - 3)) * CH;
    const float* swp = &sw[lane * 2];

    // x-interior test: all 14 window cols in [0,64)  (warp-uniform)
    const bool xfull = (x0 >= 3) && (x0 + 10 < HW);

    // Sliding row window: 10 input rows feed the 4 output rows (RY+6).
    #pragma unroll
    for (int riy = 0; riy < 10; ++riy) {
        const int iy = y0 - 3 + riy;
        const bool yok = ((unsigned)iy < (unsigned)HW);

        ULL rw[14];
        if (yok && xfull) {
            // fast path: 14 plain LDG.64 at immediate offsets off one base
            const float* rowp = wbase + (size_t)riy * (HW * CH);
            #pragma unroll
            for (int i = 0; i < 14; ++i)
                rw[i] = *reinterpret_cast<const ULL*>(&rowp[(size_t)i * CH]);
        } else {
            // border path: clamp + select-zero
            const float* row = xb + (size_t)iy * HW * CH;
            #pragma unroll
            for (int i = 0; i < 14; ++i) {
                const int xc = x0 - 3 + i;
                rw[i] = (yok && (unsigned)xc < (unsigned)HW)
                      ? *reinterpret_cast<const ULL*>(&row[(size_t)xc * CH])
                      : 0ULL;
            }
        }

        #pragma unroll
        for (int ky = 0; ky < 7; ++ky) {
            const int ry = riy - ky;           // compile-time after full unroll
            if (ry >= 0 && ry < 4) {
                #pragma unroll
                for (int kx = 0; kx < 7; ++kx) {
                    const ULL wk = *reinterpret_cast<const ULL*>(
                        &swp[(ky * 7 + kx) * 64]);
                    #pragma unroll
                    for (int rx = 0; rx < 8; ++rx)
                        acc[ry][rx] = ffma2(rw[rx + kx], wk, acc[ry][rx]);
                }
            }
        }
    }

    float* ob = out + ((size_t)b * NTOK + 1) * CH + c;
    #pragma unroll
    for (int ry = 0; ry < 4; ++ry)
        #pragma unroll
        for (int rx = 0; rx < 8; ++rx) {
            const size_t p = (size_t)(y0 + ry) * HW + (x0 + rx);
            *reinterpret_cast<ULL*>(&ob[p * CH]) = acc[ry][rx];
        }
}

// ---------------------------------------------------------------------------
extern "C" void kernel_launch(void* const* d_in, const int* in_sizes, int n_in,
                              void* d_out, int out_size) {
    const float* x  = (const float*)d_in[0];
    const float* w7 = (const float*)d_in[1];
    const float* b7 = (const float*)d_in[2];
    const float* w5 = (const float*)d_in[3];
    const float* b5 = (const float*)d_in[4];
    const float* w3 = (const float*)d_in[5];
    const float* b3 = (const float*)d_in[6];
    float* out = (float*)d_out;

    ppeg_prep<<<132, 256>>>(w7, b7, w5, b5, w3, b3, x, out);
    dim3 grid(4, 8, 16 * 8);                   // 16x8 tiles, RY=4
    ppeg_conv<<<grid, 128>>>(x, out);
}

// round 11
// speedup vs baseline: 1.0763x; 1.0763x over previous
#include <cuda_runtime.h>
#include <cstdint>

// PPEG: out[b,0,c] = x[b,0,c] (cls); out[b,1+p,c] = folded 7x7 depthwise conv
// (w7 + pad(w5) + pad(w3) + identity, bias b7+b5+b3) over the 64x64 map.
// R11 = RY=3 interpolation: thread = 8x3 px, tile 16x6, 128 thr, 4 CTAs/SM.
//   R9 (RY=2): 96 regs, 7 ld/px, 88.8us.  R10 (RY=4): 160 regs, 4.4 ld/px, 97.9us.
//   R11: ~128 regs capped, 5.25 ld/px, 16 warps/SM.

#define CH   512
#define HW   64
#define NTOK 4097

typedef unsigned long long ULL;

__device__ float g_weff[49 * CH];   // [tap][channel]
__device__ float g_bsum[CH];

// packed f32x2 FMA (sm_103a FFMA2 — only reachable via PTX)
__device__ __forceinline__ ULL ffma2(ULL a, ULL b, ULL c) {
    ULL d;
    asm("fma.rn.f32x2 %0, %1, %2, %3;" : "=l"(d) : "l"(a), "l"(b), "l"(c));
    return d;
}

// ---------------------------------------------------------------------------
// Kernel 1: weight fold + bias + cls copy, one launch.
__global__ void ppeg_prep(const float* __restrict__ w7, const float* __restrict__ b7,
                          const float* __restrict__ w5, const float* __restrict__ b5,
                          const float* __restrict__ w3, const float* __restrict__ b3,
                          const float* __restrict__ x, float* __restrict__ out) {
    const int bid = blockIdx.x;
    const int tid = threadIdx.x;
    if (bid < 98) {
        const int i = bid * 256 + tid;        // 0 .. 25087 = 512*49
        const int c = i / 49;
        const int t = i % 49;
        const int ky = t / 7, kx = t % 7;
        float v = w7[c * 49 + t];
        if (ky >= 1 && ky <= 5 && kx >= 1 && kx <= 5)
            v += w5[c * 25 + (ky - 1) * 5 + (kx - 1)];
        if (ky >= 2 && ky <= 4 && kx >= 2 && kx <= 4)
            v += w3[c * 9 + (ky - 2) * 3 + (kx - 2)];
        if (t == 24) v += 1.0f;               // identity (residual) term
        g_weff[t * CH + c] = v;
    } else if (bid < 100) {
        const int c = (bid - 98) * 256 + tid;
        g_bsum[c] = b7[c] + b5[c] + b3[c];
    } else {
        const int j = (bid - 100) * 256 + tid;   // cls: 16*512 floats
        const int b = j >> 9;
        const int cc = j & 511;
        const size_t off = (size_t)b * NTOK * CH + cc;
        out[off] = x[off];
    }
}

// ---------------------------------------------------------------------------
// Kernel 2: folded 7x7 depthwise conv.
//   lane   = channel pair (64 ch per block) -> 256B coalesced accesses
//   thread = 8x3 output pixels; warps 2x2 -> block tile 16x6 pixels
//   grid   = (4, 11, 128); last y-band ragged (stores predicated by y<64)
__global__ void __launch_bounds__(128, 4)
ppeg_conv(const float* __restrict__ x, float* __restrict__ out) {
    const int lane = threadIdx.x & 31;
    const int warp = threadIdx.x >> 5;         // 0..3
    const int wx = warp & 1;
    const int wy = warp >> 1;                  // 0..1
    const int x0 = blockIdx.x * 16 + wx * 8;   // RX=8 output cols per thread
    const int y0 = blockIdx.y * 6 + wy * 3;    // RY=3 output rows per thread
    const int b  = blockIdx.z >> 3;
    const int cg = blockIdx.z & 7;
    const int cb = cg * 64;
    const int c  = cb + lane * 2;

    // Stage this channel group's folded weights + bias into SMEM (coalesced).
    __shared__ __align__(16) float sw[49 * 64];
    __shared__ __align__(16) float sb[64];
    #pragma unroll
    for (int i = threadIdx.x; i < 49 * 64; i += 128) {
        const int t  = i >> 6;
        const int cc = i & 63;
        sw[i] = g_weff[t * CH + cb + cc];
    }
    if (threadIdx.x < 64) sb[threadIdx.x] = g_bsum[cb + threadIdx.x];
    __syncthreads();

    const ULL bias = *reinterpret_cast<const ULL*>(&sb[lane * 2]);

    ULL acc[3][8];
    #pragma unroll
    for (int ry = 0; ry < 3; ++ry)
        #pragma unroll
        for (int rx = 0; rx < 8; ++rx)
            acc[ry][rx] = bias;

    const float* xb = x + ((size_t)b * NTOK + 1) * CH + c;
    const float* wbase = xb + ((size_t)(y0 - 3) * HW + (x0 - 3)) * CH;
    const float* swp = &sw[lane * 2];

    // x-interior test: all 14 window cols in [0,64)  (warp-uniform)
    const bool xfull = (x0 >= 3) && (x0 + 10 < HW);

    // Sliding row window: 9 input rows feed the 3 output rows (RY+6).
    #pragma unroll
    for (int riy = 0; riy < 9; ++riy) {
        const int iy = y0 - 3 + riy;
        const bool yok = ((unsigned)iy < (unsigned)HW);

        ULL rw[14];
        if (yok && xfull) {
            // fast path: 14 plain LDG.64 at immediate offsets off one base
            const float* rowp = wbase + (size_t)riy * (HW * CH);
            #pragma unroll
            for (int i = 0; i < 14; ++i)
                rw[i] = *reinterpret_cast<const ULL*>(&rowp[(size_t)i * CH]);
        } else {
            // border path: clamp + select-zero
            const float* row = xb + (size_t)iy * HW * CH;
            #pragma unroll
            for (int i = 0; i < 14; ++i) {
                const int xc = x0 - 3 + i;
                rw[i] = (yok && (unsigned)xc < (unsigned)HW)
                      ? *reinterpret_cast<const ULL*>(&row[(size_t)xc * CH])
                      : 0ULL;
            }
        }

        #pragma unroll
        for (int ky = 0; ky < 7; ++ky) {
            const int ry = riy - ky;           // compile-time after full unroll
            if (ry >= 0 && ry < 3) {
                #pragma unroll
                for (int kx = 0; kx < 7; ++kx) {
                    const ULL wk = *reinterpret_cast<const ULL*>(
                        &swp[(ky * 7 + kx) * 64]);
                    #pragma unroll
                    for (int rx = 0; rx < 8; ++rx)
                        acc[ry][rx] = ffma2(rw[rx + kx], wk, acc[ry][rx]);
                }
            }
        }
    }

    float* ob = out + ((size_t)b * NTOK + 1) * CH + c;
    #pragma unroll
    for (int ry = 0; ry < 3; ++ry) {
        const int yy = y0 + ry;
        if (yy < HW) {                         // ragged last band
            #pragma unroll
            for (int rx = 0; rx < 8; ++rx) {
                const size_t p = (size_t)yy * HW + (x0 + rx);
                *reinterpret_cast<ULL*>(&ob[p * CH]) = acc[ry][rx];
            }
        }
    }
}

// ---------------------------------------------------------------------------
extern "C" void kernel_launch(void* const* d_in, const int* in_sizes, int n_in,
                              void* d_out, int out_size) {
    const float* x  = (const float*)d_in[0];
    const float* w7 = (const float*)d_in[1];
    const float* b7 = (const float*)d_in[2];
    const float* w5 = (const float*)d_in[3];
    const float* b5 = (const float*)d_in[4];
    const float* w3 = (const float*)d_in[5];
    const float* b3 = (const float*)d_in[6];
    float* out = (float*)d_out;

    ppeg_prep<<<132, 256>>>(w7, b7, w5, b5, w3, b3, x, out);
    dim3 grid(4, 11, 16 * 8);                  // 16x6 tiles, RY=3 (last band ragged)
    ppeg_conv<<<grid, 128>>>(x, out);
}